// round 13
// baseline (speedup 1.0000x reference)
#include <cuda_runtime.h>
#include <cstdint>

#define Bv 4
#define Sv 4096
#define Hv 32
#define Dv 64
#define NSTEPS 128
#define ROWSTRIDE (Hv * Dv)       // 2048 floats between consecutive s
#define TILE 64                   // rows per half-tile (4 per warp, 16 warps)
#define NTILES (Sv / TILE)        // 64
#define HTILES (NTILES / 2)       // 32 tiles per half
#define TILE_FLOATS (TILE * Dv)   // 4096 floats = 16 KB
#define NBUF 3
#define FULL 0xffffffffu
#define PADP 33

// sum across the 8 lanes of a row-group (lanes g*8..g*8+7)
__device__ __forceinline__ float grp8_sum(float v) {
    v += __shfl_xor_sync(FULL, v, 4);
    v += __shfl_xor_sync(FULL, v, 2);
    v += __shfl_xor_sync(FULL, v, 1);
    return v;
}
// inclusive scan across the 4 row-groups (stride-8 lanes)
__device__ __forceinline__ float scan_grp(float v, int lane) {
    float t = __shfl_up_sync(FULL, v, 8);
    if (lane >= 8) v += t;
    t = __shfl_up_sync(FULL, v, 16);
    if (lane >= 16) v += t;
    return v;
}
__device__ __forceinline__ float4 relu4(float4 a) {
    return make_float4(fmaxf(a.x, 0.f), fmaxf(a.y, 0.f),
                       fmaxf(a.z, 0.f), fmaxf(a.w, 0.f));
}
__device__ __forceinline__ float dot4(float4 a, float4 b) {
    return fmaf(a.x, b.x, fmaf(a.y, b.y, fmaf(a.z, b.z, a.w * b.w)));
}
__device__ __forceinline__ void cp16(float* dst_smem, const float* src) {
    uint32_t d = (uint32_t)__cvta_generic_to_shared(dst_smem);
    asm volatile("cp.async.cg.shared.global [%0], [%1], 16;"
                 :: "r"(d), "l"(src) : "memory");
}
__device__ __forceinline__ void nbar_sync(int id, int cnt) {
    asm volatile("bar.sync %0, %1;" :: "r"(id), "r"(cnt) : "memory");
}
__device__ __forceinline__ void nbar_arrive(int id, int cnt) {
    asm volatile("bar.arrive %0, %1;" :: "r"(id), "r"(cnt) : "memory");
}

__global__ __launch_bounds__(1024, 1)
void rope_ctx_kernel(const float* __restrict__ q,
                     const float* __restrict__ k,
                     const float* __restrict__ cos_step,
                     const float* __restrict__ sin_step,
                     float* __restrict__ out)
{
    extern __shared__ float smem[];   // [H][NBUF][TILE][64] for k, then for q

    __shared__ float2 s_tab[NSTEPS];
    __shared__ float  s_agg[2][64][17];
    __shared__ float  s_pref[2][64][PADP];   // [d][hw+1] incl; [d][0]=0
    // handoff double-buffered by producer tile-index parity:
    __shared__ __align__(16) float s_hand[2][2][64];

    const int tid  = threadIdx.x;
    const int w    = tid >> 5;
    const int lane = tid & 31;
    const int H    = w >> 4;               // half 0: even tiles, 1: odd tiles
    const int hw   = w & 15;               // warp within half
    const int g    = lane >> 3;            // row group 0..3
    const int j    = lane & 7;             // dim slot within row
    const int b    = blockIdx.x >> 5;      // 32 heads
    const int h    = blockIdx.x & 31;

    float* skH = smem + (size_t)H * NBUF * TILE_FLOATS;
    float* sqH = smem + 2 * NBUF * TILE_FLOATS + (size_t)H * NBUF * TILE_FLOATS;

    if (tid < NSTEPS) {
        s_tab[tid] = make_float2(cos_step[tid * Dv], sin_step[tid * Dv]);
    }
    if ((tid & 511) < 64) s_pref[H][tid & 63][0] = 0.f;   // constant thereafter

    const size_t base = (size_t)b * Sv * ROWSTRIDE + (size_t)h * Dv;
    const float* qg = q + base;
    const float* kg = k + base;
    float* og = out + base;
    const size_t KOUT = (size_t)Bv * Sv * ROWSTRIDE;

    const int dx = 4 * j;
    const int dy = 32 + 4 * j;
    const int r  = (hw << 2) + g;          // row within a 64-row tile
    const int sodx = (r << 6) + dx;
    const int sody = (r << 6) + dy;

    // per-thread-exact staging: a thread copies ONLY the words it will read,
    // so cp.async.wait_group alone (no barrier) makes them visible to it.
    auto issue = [&](int t, int p) {
        if (t < NTILES) {
            float* skb = skH + p * TILE_FLOATS;
            float* sqb = sqH + p * TILE_FLOATS;
            const size_t go = (size_t)(t * TILE + r) * ROWSTRIDE;
            cp16(skb + sodx, kg + go + dx);
            cp16(skb + sody, kg + go + dy);
            cp16(sqb + sodx, qg + go + dx);
            cp16(sqb + sody, qg + go + dy);
        }
        asm volatile("cp.async.commit_group;" ::: "memory");
    };

    int t = H;                              // this half's first tile
    issue(t, 0);
    issue(t + 2, 1);
    issue(t + 4, 2);

    const int bar_int = 1 + H;              // internal half barrier (512)
    const int bar_pub = 3 + H;              // this half publishes on it
    const int bar_con = 4 - H;              // this half consumes on it

    int p = 0;                              // buffer index, wraps mod NBUF
    for (int i = 0; i < HTILES; ++i, t += 2) {
        asm volatile("cp.async.wait_group 2;" ::: "memory");   // tile t resident

        const float* skb = skH + p * TILE_FLOATS;
        const float* sqb = sqH + p * TILE_FLOATS;
        float4 kx = *(const float4*)(skb + sodx);
        float4 ky = *(const float4*)(skb + sody);
        float4 qx = *(const float4*)(sqb + sodx);
        float4 qy = *(const float4*)(sqb + sody);

        issue(t + 6, p);            // refill just-read buffer (regs hold data)
        p = (p == NBUF - 1) ? 0 : p + 1;

        // ---- k: relu + norm ------------------------------------------------
        float4 knx = relu4(kx), kny = relu4(ky);
        float ss = grp8_sum(dot4(knx, knx) + dot4(kny, kny));
        float kinv = rsqrtf(fmaxf(ss, 1e-24f));
        knx.x *= kinv; knx.y *= kinv; knx.z *= kinv; knx.w *= kinv;
        kny.x *= kinv; kny.y *= kinv; kny.z *= kinv; kny.w *= kinv;

        // ---- in-warp inclusive scan across the 4 rows ----------------------
        float4 ix, iy;
        ix.x = scan_grp(knx.x, lane); ix.y = scan_grp(knx.y, lane);
        ix.z = scan_grp(knx.z, lane); ix.w = scan_grp(knx.w, lane);
        iy.x = scan_grp(kny.x, lane); iy.y = scan_grp(kny.y, lane);
        iy.z = scan_grp(kny.z, lane); iy.w = scan_grp(kny.w, lane);

        if (g == 3) {               // group 3 holds the warp's 4-row totals
            s_agg[H][dx    ][hw] = ix.x; s_agg[H][dx + 1][hw] = ix.y;
            s_agg[H][dx + 2][hw] = ix.z; s_agg[H][dx + 3][hw] = ix.w;
            s_agg[H][dy    ][hw] = iy.x; s_agg[H][dy + 1][hw] = iy.y;
            s_agg[H][dy + 2][hw] = iy.z; s_agg[H][dy + 3][hw] = iy.w;
        }

        float4 qrx = relu4(qx), qry = relu4(qy);
        float qs = grp8_sum(dot4(qrx, qrx) + dot4(qry, qry));
        float qinv = rsqrtf(fmaxf(qs, 1e-24f));

        const bool first = (H == 0) && (i == 0);
        const bool pubok = (H == 0) || (i < HTILES - 1);
        const int  sl = i & 1;                              // own publish slot
        const int  cs = (H == 1) ? (i & 1) : ((i + 1) & 1); // consume slot

        if (!first) nbar_sync(bar_con, 1024);   // other half's base published

        nbar_sync(bar_int, 512);    // B1: s_agg[H] ready

        // ---- cross-warp scan + EARLY publish (lane 15 holds the total) -----
        #pragma unroll
        for (int dd = 0; dd < 4; ++dd) {
            const int d = 4 * hw + dd;
            float v = (lane < 16) ? s_agg[H][d][lane] : 0.f;
            float u;
            u = __shfl_up_sync(FULL, v, 1);  if (lane >= 1) v += u;
            u = __shfl_up_sync(FULL, v, 2);  if (lane >= 2) v += u;
            u = __shfl_up_sync(FULL, v, 4);  if (lane >= 4) v += u;
            u = __shfl_up_sync(FULL, v, 8);  if (lane >= 8) v += u;
            if (lane < 16) s_pref[H][d][lane + 1] = v;  // excl at [hw]
            if (pubok && lane == 15) {
                float pb = first ? 0.f : s_hand[1 - H][cs][d];
                s_hand[H][sl][d] = pb + v;    // base for the other half's tile
            }
        }
        __threadfence_block();
        if (pubok) nbar_arrive(bar_pub, 1024);  // release the other half NOW

        nbar_sync(bar_int, 512);    // B2: s_pref[H] ready

        // ---- epilogue: base (slot still valid — 2-tile overwrite distance) -
        float4 basex, basey;
        if (first) {
            basex = make_float4(0.f, 0.f, 0.f, 0.f);
            basey = make_float4(0.f, 0.f, 0.f, 0.f);
        } else {
            const float* hb = &s_hand[1 - H][cs][0];
            basex = *(const float4*)(hb + dx);
            basey = *(const float4*)(hb + dy);
        }

        float4 cx, cy;
        cx.x = basex.x + s_pref[H][dx    ][hw] + ix.x;
        cx.y = basex.y + s_pref[H][dx + 1][hw] + ix.y;
        cx.z = basex.z + s_pref[H][dx + 2][hw] + ix.z;
        cx.w = basex.w + s_pref[H][dx + 3][hw] + ix.w;
        cy.x = basey.x + s_pref[H][dy    ][hw] + iy.x;
        cy.y = basey.y + s_pref[H][dy + 1][hw] + iy.y;
        cy.z = basey.z + s_pref[H][dy + 2][hw] + iy.z;
        cy.w = basey.w + s_pref[H][dy + 3][hw] + iy.w;

        float dot = grp8_sum(dot4(qrx, cx) + dot4(qry, cy)) * qinv;

        float pp = fminf(fmaxf(dot * (1.f / 32.f), 0.f), 127.f);
        float pf = floorf(pp);
        int   fi = (int)pf;
        int   ci = (int)ceilf(pp);
        float fr = pp - pf;
        float2 t0 = s_tab[fi], t1 = s_tab[ci];
        float cn = fmaf(fr, t1.x - t0.x, t0.x);
        float sn = fmaf(fr, t1.y - t0.y, t0.y);

        float4 oqx, oqy, okx, oky;
        oqx.x = fmaf(qx.x, cn, -qy.x * sn);  oqy.x = fmaf(qy.x, cn, qx.x * sn);
        oqx.y = fmaf(qx.y, cn, -qy.y * sn);  oqy.y = fmaf(qy.y, cn, qx.y * sn);
        oqx.z = fmaf(qx.z, cn, -qy.z * sn);  oqy.z = fmaf(qy.z, cn, qx.z * sn);
        oqx.w = fmaf(qx.w, cn, -qy.w * sn);  oqy.w = fmaf(qy.w, cn, qx.w * sn);
        okx.x = fmaf(kx.x, cn, -ky.x * sn);  oky.x = fmaf(ky.x, cn, kx.x * sn);
        okx.y = fmaf(kx.y, cn, -ky.y * sn);  oky.y = fmaf(ky.y, cn, kx.y * sn);
        okx.z = fmaf(kx.z, cn, -ky.z * sn);  oky.z = fmaf(ky.z, cn, kx.z * sn);
        okx.w = fmaf(kx.w, cn, -ky.w * sn);  oky.w = fmaf(ky.w, cn, kx.w * sn);

        const size_t ro = (size_t)(t * TILE + r) * ROWSTRIDE + dx;
        __stcs((float4*)(og + ro),             oqx);
        __stcs((float4*)(og + ro + 32),        oqy);
        __stcs((float4*)(og + KOUT + ro),      okx);
        __stcs((float4*)(og + KOUT + ro + 32), oky);
    }
}

extern "C" void kernel_launch(void* const* d_in, const int* in_sizes, int n_in,
                              void* d_out, int out_size)
{
    const float* q        = (const float*)d_in[0];
    const float* k        = (const float*)d_in[1];
    // d_in[2] = v (unused by the reference math)
    const float* cos_step = (const float*)d_in[3];
    const float* sin_step = (const float*)d_in[4];
    // d_in[5] = offset (unused by the reference math)

    const size_t dyn = (size_t)4 * NBUF * TILE_FLOATS * sizeof(float); // 192 KB
    cudaFuncSetAttribute(rope_ctx_kernel,
                         cudaFuncAttributeMaxDynamicSharedMemorySize, (int)dyn);
    rope_ctx_kernel<<<Bv * Hv, 1024, dyn>>>(q, k, cos_step, sin_step,
                                            (float*)d_out);
}

// round 14
// speedup vs baseline: 1.0484x; 1.0484x over previous
#include <cuda_runtime.h>
#include <cstdint>

#define Bv 4
#define Sv 4096
#define Hv 32
#define Dv 64
#define NSTEPS 128
#define ROWSTRIDE (Hv * Dv)       // 2048 floats between consecutive s
#define TILE 64                   // rows per half-tile (4 per warp, 16 warps)
#define NTILES (Sv / TILE)        // 64
#define HTILES (NTILES / 2)       // 32 tiles per half
#define TILE_FLOATS (TILE * Dv)   // 4096 floats = 16 KB
#define FULL 0xffffffffu
#define OSTRIDE ((size_t)2 * TILE * ROWSTRIDE)   // output advance per tile

// sum across the 8 lanes of a row-group (lanes g*8..g*8+7)
__device__ __forceinline__ float grp8_sum(float v) {
    v += __shfl_xor_sync(FULL, v, 4);
    v += __shfl_xor_sync(FULL, v, 2);
    v += __shfl_xor_sync(FULL, v, 1);
    return v;
}
// inclusive scan across the 4 row-groups (stride-8 lanes)
__device__ __forceinline__ float scan_grp(float v, int lane) {
    float t = __shfl_up_sync(FULL, v, 8);
    if (lane >= 8) v += t;
    t = __shfl_up_sync(FULL, v, 16);
    if (lane >= 16) v += t;
    return v;
}
__device__ __forceinline__ float4 relu4(float4 a) {
    return make_float4(fmaxf(a.x, 0.f), fmaxf(a.y, 0.f),
                       fmaxf(a.z, 0.f), fmaxf(a.w, 0.f));
}
__device__ __forceinline__ float dot4(float4 a, float4 b) {
    return fmaf(a.x, b.x, fmaf(a.y, b.y, fmaf(a.z, b.z, a.w * b.w)));
}
__device__ __forceinline__ void cp16(float* dst_smem, const float* src) {
    uint32_t d = (uint32_t)__cvta_generic_to_shared(dst_smem);
    asm volatile("cp.async.cg.shared.global [%0], [%1], 16;"
                 :: "r"(d), "l"(src) : "memory");
}
__device__ __forceinline__ void nbar_sync(int id, int cnt) {
    asm volatile("bar.sync %0, %1;" :: "r"(id), "r"(cnt) : "memory");
}
__device__ __forceinline__ void nbar_arrive(int id, int cnt) {
    asm volatile("bar.arrive %0, %1;" :: "r"(id), "r"(cnt) : "memory");
}

__global__ __launch_bounds__(1024, 1)
void rope_ctx_kernel(const float* __restrict__ q,
                     const float* __restrict__ k,
                     const float* __restrict__ cos_step,
                     const float* __restrict__ sin_step,
                     float* __restrict__ out)
{
    extern __shared__ float smem[];     // [half][2 buf][TILE][64] for k, then q

    __shared__ float2 s_tab[NSTEPS];
    __shared__ float  s_agg[2][64][17];
    // TRANSPOSED prefix: row = warp index (0..16), col = dim (pad 68)
    __shared__ __align__(16) float s_pref[2][17][68];
    __shared__ __align__(16) float s_hand[2][64];  // base published by half H

    const int tid  = threadIdx.x;
    const int w    = tid >> 5;
    const int lane = tid & 31;
    const int H    = w >> 4;               // half 0: even tiles, 1: odd tiles
    const int hw   = w & 15;               // warp within half
    const int g    = lane >> 3;            // row group 0..3
    const int j    = lane & 7;             // dim slot within row
    const int b    = blockIdx.x >> 5;      // 32 heads
    const int h    = blockIdx.x & 31;

    float* skH = smem + (size_t)H * 2 * TILE_FLOATS;
    float* sqH = smem + 4 * TILE_FLOATS + (size_t)H * 2 * TILE_FLOATS;

    if (tid < NSTEPS) {
        s_tab[tid] = make_float2(cos_step[tid * Dv], sin_step[tid * Dv]);
    }
    if ((tid & 511) < 64) s_pref[H][0][tid & 63] = 0.f;   // constant thereafter

    const size_t base = (size_t)b * Sv * ROWSTRIDE + (size_t)h * Dv;
    const float* qg = q + base;
    const float* kg = k + base;
    float* og = out + base;
    const size_t KOUT = (size_t)Bv * Sv * ROWSTRIDE;

    const int dx = 4 * j;
    const int dy = 32 + 4 * j;
    const int r  = (hw << 2) + g;          // row within a 64-row tile
    const int sodx = (r << 6) + dx;
    const int sody = (r << 6) + dy;

    // per-thread-exact staging: a thread copies ONLY the words it will read,
    // so cp.async.wait_group alone (no barrier) makes them visible to it.
    auto issue = [&](int t, int p) {
        if (t < NTILES) {
            float* skb = skH + p * TILE_FLOATS;
            float* sqb = sqH + p * TILE_FLOATS;
            const size_t go = (size_t)(t * TILE + r) * ROWSTRIDE;
            cp16(skb + sodx, kg + go + dx);
            cp16(skb + sody, kg + go + dy);
            cp16(sqb + sodx, qg + go + dx);
            cp16(sqb + sody, qg + go + dy);
        }
        asm volatile("cp.async.commit_group;" ::: "memory");
    };

    int t = H;                              // this half's first tile
    issue(t, 0);
    issue(t + 2, 1);

    const int bar_int = 1 + H;              // internal half barrier (512)
    const int bar_pub = 3 + H;              // this half publishes on it
    const int bar_con = 4 - H;              // this half consumes on it

    // hoisted output pointers (advance by constant stride per tile)
    float* oqp = og + (size_t)(t * TILE + r) * ROWSTRIDE + dx;
    float* okp = oqp + KOUT;

    for (int i = 0; i < HTILES; ++i, t += 2) {
        const int p = i & 1;
        asm volatile("cp.async.wait_group 1;" ::: "memory");   // tile t resident

        const float* skb = skH + p * TILE_FLOATS;
        const float* sqb = sqH + p * TILE_FLOATS;
        float4 kx = *(const float4*)(skb + sodx);
        float4 ky = *(const float4*)(skb + sody);
        float4 qx = *(const float4*)(sqb + sodx);
        float4 qy = *(const float4*)(sqb + sody);

        issue(t + 4, p);            // refill just-consumed buffer (regs hold data)

        // ---- k: relu + norm -------------------------------------------------
        float4 knx = relu4(kx), kny = relu4(ky);
        float ss = grp8_sum(dot4(knx, knx) + dot4(kny, kny));
        float kinv = rsqrtf(fmaxf(ss, 1e-24f));
        knx.x *= kinv; knx.y *= kinv; knx.z *= kinv; knx.w *= kinv;
        kny.x *= kinv; kny.y *= kinv; kny.z *= kinv; kny.w *= kinv;

        // ---- in-warp inclusive scan across the 4 rows ----------------------
        float4 ix, iy;
        ix.x = scan_grp(knx.x, lane); ix.y = scan_grp(knx.y, lane);
        ix.z = scan_grp(knx.z, lane); ix.w = scan_grp(knx.w, lane);
        iy.x = scan_grp(kny.x, lane); iy.y = scan_grp(kny.y, lane);
        iy.z = scan_grp(kny.z, lane); iy.w = scan_grp(kny.w, lane);

        if (g == 3) {               // group 3 holds the warp's 4-row totals
            s_agg[H][dx    ][hw] = ix.x; s_agg[H][dx + 1][hw] = ix.y;
            s_agg[H][dx + 2][hw] = ix.z; s_agg[H][dx + 3][hw] = ix.w;
            s_agg[H][dy    ][hw] = iy.x; s_agg[H][dy + 1][hw] = iy.y;
            s_agg[H][dy + 2][hw] = iy.z; s_agg[H][dy + 3][hw] = iy.w;
        }

        float4 qrx = relu4(qx), qry = relu4(qy);
        float qs = grp8_sum(dot4(qrx, qrx) + dot4(qry, qry));
        float qinv = rsqrtf(fmaxf(qs, 1e-24f));

        nbar_sync(bar_int, 512);    // B1: s_agg[H] published

        // ---- cross-warp scan: warp hw scans dims 4hw..4hw+3 over 16 entries
        #pragma unroll
        for (int dd = 0; dd < 4; ++dd) {
            const int d = 4 * hw + dd;
            float v = (lane < 16) ? s_agg[H][d][lane] : 0.f;
            float u;
            u = __shfl_up_sync(FULL, v, 1);  if (lane >= 1) v += u;
            u = __shfl_up_sync(FULL, v, 2);  if (lane >= 2) v += u;
            u = __shfl_up_sync(FULL, v, 4);  if (lane >= 4) v += u;
            u = __shfl_up_sync(FULL, v, 8);  if (lane >= 8) v += u;
            if (lane < 16) s_pref[H][lane + 1][d] = v;  // excl at row hw, tot row 16
        }
        nbar_sync(bar_int, 512);    // B2: s_pref[H] ready

        // ---- cross-half handoff (verbatim R12 choreography) ----------------
        const bool first = (i == 0) && (H == 0);
        float4 basex, basey;
        if (!first) {
            nbar_sync(bar_con, 1024);            // wait other half's publish
            basex = *(const float4*)&s_hand[1 - H][dx];
            basey = *(const float4*)&s_hand[1 - H][dy];
        } else {
            basex = make_float4(0.f, 0.f, 0.f, 0.f);
            basey = make_float4(0.f, 0.f, 0.f, 0.f);
        }
        if (H == 0 || i < HTILES - 1) {          // last B tile has no consumer
            if (hw == 0 && lane < 16) {
                const int d = 4 * lane;
                float4 pb = first ? make_float4(0.f, 0.f, 0.f, 0.f)
                                  : *(const float4*)&s_hand[1 - H][d];
                float4 tt = *(const float4*)&s_pref[H][16][d];  // tile totals
                float4 nb;
                nb.x = pb.x + tt.x;
                nb.y = pb.y + tt.y;
                nb.z = pb.z + tt.z;
                nb.w = pb.w + tt.w;
                *(float4*)&s_hand[H][d] = nb;    // base(t+1) for the other half
            }
            if (hw == 0) __threadfence_block();
            nbar_arrive(bar_pub, 1024);          // all 512 of this half arrive
        }

        // ---- epilogue: assemble cum (two LDS.128), dot, rope, store ---------
        const float4 px = *(const float4*)&s_pref[H][hw][dx];
        const float4 py = *(const float4*)&s_pref[H][hw][dy];
        float4 cx, cy;
        cx.x = basex.x + px.x + ix.x;  cx.y = basex.y + px.y + ix.y;
        cx.z = basex.z + px.z + ix.z;  cx.w = basex.w + px.w + ix.w;
        cy.x = basey.x + py.x + iy.x;  cy.y = basey.y + py.y + iy.y;
        cy.z = basey.z + py.z + iy.z;  cy.w = basey.w + py.w + iy.w;

        float dot = grp8_sum(dot4(qrx, cx) + dot4(qry, cy)) * qinv;

        float pp = fminf(fmaxf(dot * (1.f / 32.f), 0.f), 127.f);
        float pf = floorf(pp);
        int   fi = (int)pf;
        int   ci = (int)ceilf(pp);
        float fr = pp - pf;
        float2 t0 = s_tab[fi], t1 = s_tab[ci];
        float cn = fmaf(fr, t1.x - t0.x, t0.x);
        float sn = fmaf(fr, t1.y - t0.y, t0.y);

        float4 oqx, oqy, okx, oky;
        oqx.x = fmaf(qx.x, cn, -qy.x * sn);  oqy.x = fmaf(qy.x, cn, qx.x * sn);
        oqx.y = fmaf(qx.y, cn, -qy.y * sn);  oqy.y = fmaf(qy.y, cn, qx.y * sn);
        oqx.z = fmaf(qx.z, cn, -qy.z * sn);  oqy.z = fmaf(qy.z, cn, qx.z * sn);
        oqx.w = fmaf(qx.w, cn, -qy.w * sn);  oqy.w = fmaf(qy.w, cn, qx.w * sn);
        okx.x = fmaf(kx.x, cn, -ky.x * sn);  oky.x = fmaf(ky.x, cn, kx.x * sn);
        okx.y = fmaf(kx.y, cn, -ky.y * sn);  oky.y = fmaf(ky.y, cn, kx.y * sn);
        okx.z = fmaf(kx.z, cn, -ky.z * sn);  oky.z = fmaf(ky.z, cn, kx.z * sn);
        okx.w = fmaf(kx.w, cn, -ky.w * sn);  oky.w = fmaf(ky.w, cn, kx.w * sn);

        __stcs((float4*)(oqp),      oqx);
        __stcs((float4*)(oqp + 32), oqy);
        __stcs((float4*)(okp),      okx);
        __stcs((float4*)(okp + 32), oky);
        oqp += OSTRIDE;
        okp += OSTRIDE;
    }
}

extern "C" void kernel_launch(void* const* d_in, const int* in_sizes, int n_in,
                              void* d_out, int out_size)
{
    const float* q        = (const float*)d_in[0];
    const float* k        = (const float*)d_in[1];
    // d_in[2] = v (unused by the reference math)
    const float* cos_step = (const float*)d_in[3];
    const float* sin_step = (const float*)d_in[4];
    // d_in[5] = offset (unused by the reference math)

    const size_t dyn = (size_t)8 * TILE_FLOATS * sizeof(float);  // 128 KB
    cudaFuncSetAttribute(rope_ctx_kernel,
                         cudaFuncAttributeMaxDynamicSharedMemorySize, (int)dyn);
    rope_ctx_kernel<<<Bv * Hv, 1024, dyn>>>(q, k, cos_step, sin_step,
                                            (float*)d_out);
}

// round 15
// speedup vs baseline: 1.1466x; 1.0936x over previous
#include <cuda_runtime.h>
#include <cstdint>

#define Bv 4
#define Sv 4096
#define Hv 32
#define Dv 64
#define NSTEPS 128
#define ROWSTRIDE (Hv * Dv)       // 2048 floats between consecutive s
#define TILE 64                   // rows per half-tile (4 per warp, 16 warps)
#define NTILES (Sv / TILE)        // 64
#define HTILES (NTILES / 2)       // 32 tiles per half
#define TILE_FLOATS (TILE * Dv)   // 4096 floats = 16 KB
#define FULL 0xffffffffu
#define PADP 33

// sum across the 8 lanes of a row-group (lanes g*8..g*8+7)
__device__ __forceinline__ float grp8_sum(float v) {
    v += __shfl_xor_sync(FULL, v, 4);
    v += __shfl_xor_sync(FULL, v, 2);
    v += __shfl_xor_sync(FULL, v, 1);
    return v;
}
// inclusive scan across the 4 row-groups (stride-8 lanes)
__device__ __forceinline__ float scan_grp(float v, int lane) {
    float t = __shfl_up_sync(FULL, v, 8);
    if (lane >= 8) v += t;
    t = __shfl_up_sync(FULL, v, 16);
    if (lane >= 16) v += t;
    return v;
}
__device__ __forceinline__ float4 relu4(float4 a) {
    return make_float4(fmaxf(a.x, 0.f), fmaxf(a.y, 0.f),
                       fmaxf(a.z, 0.f), fmaxf(a.w, 0.f));
}
__device__ __forceinline__ float dot4(float4 a, float4 b) {
    return fmaf(a.x, b.x, fmaf(a.y, b.y, fmaf(a.z, b.z, a.w * b.w)));
}
__device__ __forceinline__ void cp16(float* dst_smem, const float* src) {
    uint32_t d = (uint32_t)__cvta_generic_to_shared(dst_smem);
    asm volatile("cp.async.cg.shared.global [%0], [%1], 16;"
                 :: "r"(d), "l"(src) : "memory");
}
__device__ __forceinline__ void nbar_sync(int id, int cnt) {
    asm volatile("bar.sync %0, %1;" :: "r"(id), "r"(cnt) : "memory");
}
__device__ __forceinline__ void nbar_arrive(int id, int cnt) {
    asm volatile("bar.arrive %0, %1;" :: "r"(id), "r"(cnt) : "memory");
}

__global__ __launch_bounds__(1024, 1)
void rope_ctx_kernel(const float* __restrict__ q,
                     const float* __restrict__ k,
                     const float* __restrict__ cos_step,
                     const float* __restrict__ sin_step,
                     float* __restrict__ out)
{
    extern __shared__ float smem[];     // [half][2 buf][TILE][64] for k, then q

    __shared__ float2 s_tab[NSTEPS];
    __shared__ float  s_agg[2][64][17];
    __shared__ float  s_pref[2][64][PADP];  // [d][hw+1] incl; [d][0]=0; tot [16]
    __shared__ __align__(16) float s_hand[2][64];  // base published by half H

    const int tid  = threadIdx.x;
    const int w    = tid >> 5;
    const int lane = tid & 31;
    const int H    = w >> 4;               // half 0: even tiles, 1: odd tiles
    const int hw   = w & 15;               // warp within half
    const int g    = lane >> 3;            // row group 0..3
    const int j    = lane & 7;             // dim slot within row
    const int b    = blockIdx.x >> 5;      // H = 32 heads
    const int h    = blockIdx.x & 31;

    float* skH = smem + (size_t)H * 2 * TILE_FLOATS;
    float* sqH = smem + 4 * TILE_FLOATS + (size_t)H * 2 * TILE_FLOATS;

    if (tid < NSTEPS) {
        s_tab[tid] = make_float2(cos_step[tid * Dv], sin_step[tid * Dv]);
    }
    if ((tid & 511) < 64) s_pref[H][tid & 63][0] = 0.f;   // constant thereafter

    const size_t base = (size_t)b * Sv * ROWSTRIDE + (size_t)h * Dv;
    const float* qg = q + base;
    const float* kg = k + base;
    float* og = out + base;
    const size_t KOUT = (size_t)Bv * Sv * ROWSTRIDE;

    const int dx = 4 * j;
    const int dy = 32 + 4 * j;
    const int r  = (hw << 2) + g;          // row within a 64-row tile
    const int sodx = (r << 6) + dx;
    const int sody = (r << 6) + dy;

    // per-thread-exact staging: a thread copies ONLY the words it will read,
    // so cp.async.wait_group alone (no barrier) makes them visible to it.
    auto issue = [&](int t, int p) {
        if (t < NTILES) {
            float* skb = skH + p * TILE_FLOATS;
            float* sqb = sqH + p * TILE_FLOATS;
            const size_t go = (size_t)(t * TILE + r) * ROWSTRIDE;
            cp16(skb + sodx, kg + go + dx);
            cp16(skb + sody, kg + go + dy);
            cp16(sqb + sodx, qg + go + dx);
            cp16(sqb + sody, qg + go + dy);
        }
        asm volatile("cp.async.commit_group;" ::: "memory");
    };

    int t = H;                              // this half's first tile
    issue(t, 0);
    issue(t + 2, 1);

    const int bar_int  = 1 + H;             // internal half barrier (512)
    const int bar_pub  = 3 + H;             // this half publishes on it
    const int bar_con  = 4 - H;             // this half consumes on it

    for (int i = 0; i < HTILES; ++i, t += 2) {
        const int p = i & 1;
        asm volatile("cp.async.wait_group 1;" ::: "memory");   // tile t resident

        const float* skb = skH + p * TILE_FLOATS;
        const float* sqb = sqH + p * TILE_FLOATS;
        float4 kx = *(const float4*)(skb + sodx);
        float4 ky = *(const float4*)(skb + sody);
        float4 qx = *(const float4*)(sqb + sodx);
        float4 qy = *(const float4*)(sqb + sody);

        issue(t + 4, p);            // refill just-consumed buffer (regs hold data)

        // ---- k: relu + norm -------------------------------------------------
        float4 knx = relu4(kx), kny = relu4(ky);
        float ss = grp8_sum(dot4(knx, knx) + dot4(kny, kny));
        float kinv = rsqrtf(fmaxf(ss, 1e-24f));
        knx.x *= kinv; knx.y *= kinv; knx.z *= kinv; knx.w *= kinv;
        kny.x *= kinv; kny.y *= kinv; kny.z *= kinv; kny.w *= kinv;

        // ---- in-warp inclusive scan across the 4 rows ----------------------
        float4 ix, iy;
        ix.x = scan_grp(knx.x, lane); ix.y = scan_grp(knx.y, lane);
        ix.z = scan_grp(knx.z, lane); ix.w = scan_grp(knx.w, lane);
        iy.x = scan_grp(kny.x, lane); iy.y = scan_grp(kny.y, lane);
        iy.z = scan_grp(kny.z, lane); iy.w = scan_grp(kny.w, lane);

        if (g == 3) {               // group 3 holds the warp's 4-row totals
            s_agg[H][dx    ][hw] = ix.x; s_agg[H][dx + 1][hw] = ix.y;
            s_agg[H][dx + 2][hw] = ix.z; s_agg[H][dx + 3][hw] = ix.w;
            s_agg[H][dy    ][hw] = iy.x; s_agg[H][dy + 1][hw] = iy.y;
            s_agg[H][dy + 2][hw] = iy.z; s_agg[H][dy + 3][hw] = iy.w;
        }

        float4 qrx = relu4(qx), qry = relu4(qy);
        float qs = grp8_sum(dot4(qrx, qrx) + dot4(qry, qry));
        float qinv = rsqrtf(fmaxf(qs, 1e-24f));

        nbar_sync(bar_int, 512);    // B1: s_agg[H] published

        // ---- cross-warp scan: warp hw scans dims 4hw..4hw+3 over 16 entries
        #pragma unroll
        for (int dd = 0; dd < 4; ++dd) {
            const int d = 4 * hw + dd;
            float v = (lane < 16) ? s_agg[H][d][lane] : 0.f;
            float u;
            u = __shfl_up_sync(FULL, v, 1);  if (lane >= 1) v += u;
            u = __shfl_up_sync(FULL, v, 2);  if (lane >= 2) v += u;
            u = __shfl_up_sync(FULL, v, 4);  if (lane >= 4) v += u;
            u = __shfl_up_sync(FULL, v, 8);  if (lane >= 8) v += u;
            if (lane < 16) s_pref[H][d][lane + 1] = v;  // excl at [hw], tot [16]
        }
        nbar_sync(bar_int, 512);    // B2: s_pref[H] ready

        // ---- cross-half handoff --------------------------------------------
        const bool first = (i == 0) && (H == 0);
        float4 basex, basey;
        if (!first) {
            nbar_sync(bar_con, 1024);            // wait other half's publish
            basex = *(const float4*)&s_hand[1 - H][dx];
            basey = *(const float4*)&s_hand[1 - H][dy];
        } else {
            basex = make_float4(0.f, 0.f, 0.f, 0.f);
            basey = make_float4(0.f, 0.f, 0.f, 0.f);
        }
        if (H == 0 || i < HTILES - 1) {          // last B tile has no consumer
            if (hw == 0 && lane < 16) {
                const int d = 4 * lane;
                float4 pb = first ? make_float4(0.f, 0.f, 0.f, 0.f)
                                  : *(const float4*)&s_hand[1 - H][d];
                float4 nb;
                nb.x = pb.x + s_pref[H][d    ][16];
                nb.y = pb.y + s_pref[H][d + 1][16];
                nb.z = pb.z + s_pref[H][d + 2][16];
                nb.w = pb.w + s_pref[H][d + 3][16];
                *(float4*)&s_hand[H][d] = nb;    // base(t+1) for the other half
            }
            if (hw == 0) __threadfence_block();
            nbar_arrive(bar_pub, 1024);          // all 512 of this half arrive
        }

        // ---- epilogue: assemble cum, dot, position, rope, store -------------
        float4 cx, cy;
        cx.x = basex.x + s_pref[H][dx    ][hw] + ix.x;
        cx.y = basex.y + s_pref[H][dx + 1][hw] + ix.y;
        cx.z = basex.z + s_pref[H][dx + 2][hw] + ix.z;
        cx.w = basex.w + s_pref[H][dx + 3][hw] + ix.w;
        cy.x = basey.x + s_pref[H][dy    ][hw] + iy.x;
        cy.y = basey.y + s_pref[H][dy + 1][hw] + iy.y;
        cy.z = basey.z + s_pref[H][dy + 2][hw] + iy.z;
        cy.w = basey.w + s_pref[H][dy + 3][hw] + iy.w;

        float dot = grp8_sum(dot4(qrx, cx) + dot4(qry, cy)) * qinv;

        float pp = fminf(fmaxf(dot * (1.f / 32.f), 0.f), 127.f);
        float pf = floorf(pp);
        int   fi = (int)pf;
        int   ci = (int)ceilf(pp);
        float fr = pp - pf;
        float2 t0 = s_tab[fi], t1 = s_tab[ci];
        float cn = fmaf(fr, t1.x - t0.x, t0.x);
        float sn = fmaf(fr, t1.y - t0.y, t0.y);

        float4 oqx, oqy, okx, oky;
        oqx.x = fmaf(qx.x, cn, -qy.x * sn);  oqy.x = fmaf(qy.x, cn, qx.x * sn);
        oqx.y = fmaf(qx.y, cn, -qy.y * sn);  oqy.y = fmaf(qy.y, cn, qx.y * sn);
        oqx.z = fmaf(qx.z, cn, -qy.z * sn);  oqy.z = fmaf(qy.z, cn, qx.z * sn);
        oqx.w = fmaf(qx.w, cn, -qy.w * sn);  oqy.w = fmaf(qy.w, cn, qx.w * sn);
        okx.x = fmaf(kx.x, cn, -ky.x * sn);  oky.x = fmaf(ky.x, cn, kx.x * sn);
        okx.y = fmaf(kx.y, cn, -ky.y * sn);  oky.y = fmaf(ky.y, cn, kx.y * sn);
        okx.z = fmaf(kx.z, cn, -ky.z * sn);  oky.z = fmaf(ky.z, cn, kx.z * sn);
        okx.w = fmaf(kx.w, cn, -ky.w * sn);  oky.w = fmaf(ky.w, cn, kx.w * sn);

        const size_t ro = (size_t)(t * TILE + r) * ROWSTRIDE + dx;
        __stcs((float4*)(og + ro),             oqx);
        __stcs((float4*)(og + ro + 32),        oqy);
        __stcs((float4*)(og + KOUT + ro),      okx);
        __stcs((float4*)(og + KOUT + ro + 32), oky);
    }
}

extern "C" void kernel_launch(void* const* d_in, const int* in_sizes, int n_in,
                              void* d_out, int out_size)
{
    const float* q        = (const float*)d_in[0];
    const float* k        = (const float*)d_in[1];
    // d_in[2] = v (unused by the reference math)
    const float* cos_step = (const float*)d_in[3];
    const float* sin_step = (const float*)d_in[4];
    // d_in[5] = offset (unused by the reference math)

    const size_t dyn = (size_t)8 * TILE_FLOATS * sizeof(float);  // 128 KB
    cudaFuncSetAttribute(rope_ctx_kernel,
                         cudaFuncAttributeMaxDynamicSharedMemorySize, (int)dyn);
    rope_ctx_kernel<<<Bv * Hv, 1024, dyn>>>(q, k, cos_step, sin_step,
                                            (float*)d_out);
}